// round 7
// baseline (speedup 1.0000x reference)
#include <cuda_runtime.h>
#include <cuda_fp16.h>

#define NN 100000
#define NE 1280000
#define FD 64
#define NG 1000
#define BN_EPS 1e-5f
#define SCAN_CH 1024
#define SCAN_NB ((NN + SCAN_CH - 1) / SCAN_CH)   // 98

// ---------------- device scratch (allocation-free rule: __device__ globals) ----
__device__ int    g_deg[NN];
__device__ float  g_dinv[NN];
__device__ __half g_th[(size_t)NN * FD];      // transformed features (fp16 messages)
__device__ float  g_agg[(size_t)NN * FD];     // aggregated features (fp32)
__device__ float  g_stats[6 * FD];            // s1 ss1 | s2 ss2 | s3 ss3
__device__ float  g_gsum[NG * FD];
__device__ float  g_gcnt[NG];
__device__ int    g_is64;
// CSR sorted by destination; packed (src, norm-bits)
__device__ int    g_rowptr[NN + 1];
__device__ int    g_fill[NN];
__device__ int2   g_csr[NE];
__device__ int    g_bsum[SCAN_NB];
__device__ int    g_boff[SCAN_NB];

__device__ __forceinline__ unsigned pack_half2(float a, float b) {
    __half2 h = __floats2half2_rn(a, b);
    return (unsigned)__half_as_ushort(__low2half(h)) |
           ((unsigned)__half_as_ushort(__high2half(h)) << 16);
}

// ---------------- init + dtype detect (block 0 detects int64 via odd words==0)
__global__ void init_kernel(const int* __restrict__ ei) {
    int i = blockIdx.x * blockDim.x + threadIdx.x;
    if (i < NN) g_deg[i] = 0;
    if (i < 6 * FD) g_stats[i] = 0.0f;
    if (i < NG * FD) g_gsum[i] = 0.0f;
    if (i < NG) g_gcnt[i] = 0.0f;
    if (blockIdx.x == 0) {
        __shared__ int nz;
        if (threadIdx.x == 0) nz = 0;
        __syncthreads();
        int local = 0;
        for (int k = threadIdx.x; k < 4096; k += blockDim.x)
            if (ei[2 * k + 1] != 0) local = 1;
        if (local) nz = 1;
        __syncthreads();
        if (threadIdx.x == 0) g_is64 = (nz == 0) ? 1 : 0;
    }
}

__global__ void deg_kernel(const int* __restrict__ ei) {
    int e = blockIdx.x * blockDim.x + threadIdx.x;
    if (e >= NE) return;
    int c = g_is64 ? ei[2 * (NE + e)] : ei[NE + e];
    atomicAdd(&g_deg[c], 1);
}

// ---------------- rsqrt(deg+1) + per-chunk sums (scan level A) --------------
__global__ void rsqrt_scanA_kernel() {
    __shared__ int sh[256];
    int b = blockIdx.x, t = threadIdx.x;
    int base = b * SCAN_CH + t * 4;
    int s = 0;
#pragma unroll
    for (int k = 0; k < 4; k++) {
        int i = base + k;
        if (i < NN) {
            int d = g_deg[i];
            g_dinv[i] = rsqrtf((float)d + 1.0f);
            s += d;
        }
    }
    sh[t] = s;
    __syncthreads();
    for (int off = 128; off > 0; off >>= 1) {
        if (t < off) sh[t] += sh[t + off];
        __syncthreads();
    }
    if (t == 0) g_bsum[b] = sh[0];
}

__global__ void scanB_kernel() {
    if (threadIdx.x == 0) {
        int acc = 0;
        for (int b = 0; b < SCAN_NB; b++) { g_boff[b] = acc; acc += g_bsum[b]; }
        g_rowptr[NN] = acc;
    }
}

__global__ void scanC_kernel() {
    __shared__ int sh[257];
    int b = blockIdx.x, t = threadIdx.x;
    int base = b * SCAN_CH + t * 4;
    int v[4]; int s = 0;
#pragma unroll
    for (int k = 0; k < 4; k++) {
        int i = base + k;
        v[k] = (i < NN) ? g_deg[i] : 0;
        s += v[k];
    }
    sh[t + 1] = s;
    if (t == 0) sh[0] = 0;
    __syncthreads();
    for (int off = 1; off < 256; off <<= 1) {
        int val = (t + 1 > off) ? sh[t + 1 - off] : 0;
        __syncthreads();
        sh[t + 1] += val;
        __syncthreads();
    }
    int run = g_boff[b] + sh[t];
#pragma unroll
    for (int k = 0; k < 4; k++) {
        int i = base + k;
        if (i < NN) { g_rowptr[i] = run; g_fill[i] = run; run += v[k]; }
    }
}

__global__ void place_kernel(const int* __restrict__ ei) {
    int e = blockIdx.x * blockDim.x + threadIdx.x;
    if (e >= NE) return;
    int r, c;
    if (g_is64) { r = ei[2 * e]; c = ei[2 * (NE + e)]; }
    else        { r = ei[e];     c = ei[NE + e]; }
    int pos = atomicAdd(&g_fill[c], 1);
    float nrm = g_dinv[r] * g_dinv[c];
    g_csr[pos] = make_int2(r, __float_as_int(nrm));
}

// ---------------- BN stats for layer-1 input x ------------------------------
__global__ void bn_stats_x_kernel(const float* __restrict__ x) {
    int f   = threadIdx.x & 63;
    int sub = threadIdx.x >> 6;
    float s = 0.0f, ss = 0.0f;
    for (int n = blockIdx.x * 4 + sub; n < NN; n += gridDim.x * 4) {
        float v = x[(size_t)n * FD + f];
        s += v; ss += v * v;
    }
    atomicAdd(&g_stats[f], s);
    atomicAdd(&g_stats[64 + f], ss);
}

// ---------------- GEMM with fused BN fold:  t = prologue(in) @ (diag(a)W) + c@W
// prologue = relu(in + bias) if dorelu.  Output fp16.
// 64 rows/block, 256 threads, 4x4 register blocking; launch_bounds to keep
// regs <= 42 so 6 blocks/SM fit the register file (occupancy fix).
__global__ void __launch_bounds__(256, 6)
gemm_kernel(const float* __restrict__ xin, int use_agg,
            const float* __restrict__ bias, int dorelu,
            const float* __restrict__ gg, const float* __restrict__ bb,
            const float* __restrict__ W, int soff) {
    __shared__ float sIn[64 * 68];          // pad 68: float4-aligned rows, conflict-free
    __shared__ float sW[FD * FD];
    __shared__ float sA[FD], sC[FD], sCrow[FD];
    const float* __restrict__ src = use_agg ? g_agg : xin;
    int tid = threadIdx.x;

    // raw W into smem + BN fold coefficients
    for (int i = tid; i < FD * FD; i += 256) sW[i] = W[i];
    if (tid < FD) {
        float m = g_stats[soff + tid] * (1.0f / NN);
        float v = fmaxf(g_stats[soff + 64 + tid] * (1.0f / NN) - m * m, 0.0f);
        float af = gg[tid] * rsqrtf(v + BN_EPS);
        sA[tid] = af;
        sC[tid] = bb[tid] - m * af;
    }
    __syncthreads();

    // input tile load (overlapped with crow compute below)
    int base = blockIdx.x * 64;
    int nrows = min(64, NN - base);
    for (int i = tid; i < 64 * 16; i += 256) {
        int r = i >> 4, kc = i & 15;
        float4 v = make_float4(0.f, 0.f, 0.f, 0.f);
        if (r < nrows) {
            v = ((const float4*)src)[(size_t)(base + r) * 16 + kc];
            if (dorelu) {
                float4 bv = ((const float4*)bias)[kc];
                v.x = fmaxf(v.x + bv.x, 0.0f);
                v.y = fmaxf(v.y + bv.y, 0.0f);
                v.z = fmaxf(v.z + bv.z, 0.0f);
                v.w = fmaxf(v.w + bv.w, 0.0f);
            }
        }
        *((float4*)&sIn[r * 68 + kc * 4]) = v;
    }
    float cr = 0.0f;
    if (tid < FD) {
        for (int i = 0; i < FD; i++) cr += sC[i] * sW[i * FD + tid];
    }
    __syncthreads();

    // scale sW in place, publish crow
    for (int i = tid; i < FD * FD; i += 256) sW[i] *= sA[i >> 6];
    if (tid < FD) sCrow[tid] = cr;
    __syncthreads();

    int rp = tid >> 4, tc = tid & 15;      // rp: 4-row group, tc: 4-col group
    int rbase = rp * 4;
    float4 acc0 = make_float4(0.f, 0.f, 0.f, 0.f);
    float4 acc1 = make_float4(0.f, 0.f, 0.f, 0.f);
    float4 acc2 = make_float4(0.f, 0.f, 0.f, 0.f);
    float4 acc3 = make_float4(0.f, 0.f, 0.f, 0.f);
    const float4* sW4 = (const float4*)sW;
#pragma unroll
    for (int k = 0; k < FD; k++) {
        float4 w = sW4[k * 16 + tc];
        float x0 = sIn[(rbase + 0) * 68 + k];
        float x1 = sIn[(rbase + 1) * 68 + k];
        float x2 = sIn[(rbase + 2) * 68 + k];
        float x3 = sIn[(rbase + 3) * 68 + k];
        acc0.x += x0 * w.x; acc0.y += x0 * w.y; acc0.z += x0 * w.z; acc0.w += x0 * w.w;
        acc1.x += x1 * w.x; acc1.y += x1 * w.y; acc1.z += x1 * w.z; acc1.w += x1 * w.w;
        acc2.x += x2 * w.x; acc2.y += x2 * w.y; acc2.z += x2 * w.z; acc2.w += x2 * w.w;
        acc3.x += x3 * w.x; acc3.y += x3 * w.y; acc3.z += x3 * w.z; acc3.w += x3 * w.w;
    }
    float4 crw = ((const float4*)sCrow)[tc];
    acc0.x += crw.x; acc0.y += crw.y; acc0.z += crw.z; acc0.w += crw.w;
    acc1.x += crw.x; acc1.y += crw.y; acc1.z += crw.z; acc1.w += crw.w;
    acc2.x += crw.x; acc2.y += crw.y; acc2.z += crw.z; acc2.w += crw.w;
    acc3.x += crw.x; acc3.y += crw.y; acc3.z += crw.z; acc3.w += crw.w;

    uint2* th2 = (uint2*)g_th;
    if (rbase + 0 < nrows) th2[(size_t)(base + rbase + 0) * 16 + tc] = make_uint2(pack_half2(acc0.x, acc0.y), pack_half2(acc0.z, acc0.w));
    if (rbase + 1 < nrows) th2[(size_t)(base + rbase + 1) * 16 + tc] = make_uint2(pack_half2(acc1.x, acc1.y), pack_half2(acc1.z, acc1.w));
    if (rbase + 2 < nrows) th2[(size_t)(base + rbase + 2) * 16 + tc] = make_uint2(pack_half2(acc2.x, acc2.y), pack_half2(acc2.z, acc2.w));
    if (rbase + 3 < nrows) th2[(size_t)(base + rbase + 3) * 16 + tc] = make_uint2(pack_half2(acc3.x, acc3.y), pack_half2(acc3.z, acc3.w));
}

// ---------------- CSR gather conv: warp/node, lane = 2 feats, fp16 messages.
// 4-wide edge batches: CSR records fetched first, then 4 independent feature
// loads in flight (MLP=4 against L2 latency).
// Optional epilogue: BN stats of relu(agg + bias) via block reduction.
__global__ void gather_kernel(int do_stats, const float* __restrict__ bias, int soff) {
    __shared__ float sStat[128];
    int tid  = threadIdx.x;
    int lane = tid & 31;
    if (do_stats && tid < 128) sStat[tid] = 0.0f;

    int n = (blockIdx.x * blockDim.x + tid) >> 5;   // 16 nodes per 512-thread block
    const __half2* th2 = (const __half2*)g_th;
    float d = g_dinv[n];
    float s = d * d;
    float2 acc = __half22float2(th2[(size_t)n * 32 + lane]);
    acc.x *= s; acc.y *= s;

    int j = g_rowptr[n], end = g_rowptr[n + 1];
    for (; j + 4 <= end; j += 4) {
        int2 p0 = g_csr[j];
        int2 p1 = g_csr[j + 1];
        int2 p2 = g_csr[j + 2];
        int2 p3 = g_csr[j + 3];
        float2 v0 = __half22float2(th2[(size_t)p0.x * 32 + lane]);
        float2 v1 = __half22float2(th2[(size_t)p1.x * 32 + lane]);
        float2 v2 = __half22float2(th2[(size_t)p2.x * 32 + lane]);
        float2 v3 = __half22float2(th2[(size_t)p3.x * 32 + lane]);
        float w0 = __int_as_float(p0.y), w1 = __int_as_float(p1.y);
        float w2 = __int_as_float(p2.y), w3 = __int_as_float(p3.y);
        acc.x += v0.x * w0 + v1.x * w1 + v2.x * w2 + v3.x * w3;
        acc.y += v0.y * w0 + v1.y * w1 + v2.y * w2 + v3.y * w3;
    }
    if (j + 2 <= end) {
        int2 p0 = g_csr[j];
        int2 p1 = g_csr[j + 1];
        float2 v0 = __half22float2(th2[(size_t)p0.x * 32 + lane]);
        float2 v1 = __half22float2(th2[(size_t)p1.x * 32 + lane]);
        float w0 = __int_as_float(p0.y), w1 = __int_as_float(p1.y);
        acc.x += v0.x * w0 + v1.x * w1;
        acc.y += v0.y * w0 + v1.y * w1;
        j += 2;
    }
    if (j < end) {
        int2 p = g_csr[j];
        float2 v = __half22float2(th2[(size_t)p.x * 32 + lane]);
        float w = __int_as_float(p.y);
        acc.x += v.x * w;
        acc.y += v.y * w;
    }
    ((float2*)g_agg)[(size_t)n * 32 + lane] = acc;

    if (do_stats) {
        float2 bb = ((const float2*)bias)[lane];
        float y0 = fmaxf(acc.x + bb.x, 0.0f);
        float y1 = fmaxf(acc.y + bb.y, 0.0f);
        __syncthreads();             // zero-fill visible, all accs done
        atomicAdd(&sStat[2 * lane],      y0);
        atomicAdd(&sStat[2 * lane + 1],  y1);
        atomicAdd(&sStat[64 + 2 * lane],     y0 * y0);
        atomicAdd(&sStat[64 + 2 * lane + 1], y1 * y1);
        __syncthreads();
        if (tid < 128) atomicAdd(&g_stats[soff + tid], sStat[tid]);
    }
}

// ---------------- pool: y=relu(agg+b2); BN3 stats + per-graph sums (batch sorted)
__global__ void pool_kernel(const float* __restrict__ bias, const int* __restrict__ batch) {
    int f   = threadIdx.x & 63;
    int sub = threadIdx.x >> 6;
    int is64 = g_is64;
    float bs = bias[f];
    const int chunk = 196;                 // 512 blocks * 196 >= NN
    const int subc  = 49;
    int start = blockIdx.x * chunk + sub * subc;
    int stop  = min(start + subc, NN);
    float s = 0.0f, ss = 0.0f;
    int   cur = -1;
    float gv = 0.0f, gc = 0.0f;
    for (int n = start; n < stop; n++) {
        int b = is64 ? batch[2 * n] : batch[n];
        if (b != cur) {
            if (cur >= 0) {
                atomicAdd(&g_gsum[cur * FD + f], gv);
                if (f == 0) atomicAdd(&g_gcnt[cur], gc);
            }
            cur = b; gv = 0.0f; gc = 0.0f;
        }
        float v = fmaxf(g_agg[(size_t)n * FD + f] + bs, 0.0f);
        s += v; ss += v * v;
        gv += v; gc += 1.0f;
    }
    if (cur >= 0) {
        atomicAdd(&g_gsum[cur * FD + f], gv);
        if (f == 0) atomicAdd(&g_gcnt[cur], gc);
    }
    atomicAdd(&g_stats[256 + f], s);
    atomicAdd(&g_stats[320 + f], ss);
}

// ---------------- final: fold BN3 into Wout, emit [NG, 2] --------------------
__global__ void final_kernel(const float* __restrict__ gg, const float* __restrict__ bb,
                             const float* __restrict__ Wout, const float* __restrict__ bout,
                             float* __restrict__ out) {
    __shared__ float sWp[FD * 2];
    __shared__ float sc[FD];
    __shared__ float scb[2];
    int tid = threadIdx.x;
    if (tid < FD) {
        float m = g_stats[256 + tid] * (1.0f / NN);
        float v = fmaxf(g_stats[320 + tid] * (1.0f / NN) - m * m, 0.0f);
        float af = gg[tid] * rsqrtf(v + BN_EPS);
        sc[tid] = bb[tid] - m * af;
        sWp[tid * 2]     = af * Wout[tid * 2];
        sWp[tid * 2 + 1] = af * Wout[tid * 2 + 1];
    }
    __syncthreads();
    if (tid < 2) {
        float acc = bout[tid];
        for (int i = 0; i < FD; i++) acc += sc[i] * Wout[i * 2 + tid];
        scb[tid] = acc;
    }
    __syncthreads();
    int g = blockIdx.x * blockDim.x + tid;
    if (g >= NG) return;
    float cnt = g_gcnt[g];
    if (cnt > 0.0f) {
        float inv = 1.0f / cnt;
        float a0 = scb[0], a1 = scb[1];
#pragma unroll 8
        for (int f = 0; f < FD; f++) {
            float p = g_gsum[g * FD + f] * inv;
            a0 += p * sWp[f * 2];
            a1 += p * sWp[f * 2 + 1];
        }
        out[g * 2] = a0; out[g * 2 + 1] = a1;
    } else {
        out[g * 2] = bout[0]; out[g * 2 + 1] = bout[1];
    }
}

extern "C" void kernel_launch(void* const* d_in, const int* in_sizes, int n_in,
                              void* d_out, int out_size) {
    const float* x       = (const float*)d_in[0];
    const int*   ei      = (const int*)d_in[1];
    const int*   batch   = (const int*)d_in[2];
    const float* bn_in_g = (const float*)d_in[3];
    const float* bn_in_b = (const float*)d_in[4];
    const float* W1      = (const float*)d_in[5];
    const float* b1      = (const float*)d_in[6];
    const float* g1      = (const float*)d_in[7];
    const float* be1     = (const float*)d_in[8];
    const float* W2      = (const float*)d_in[9];
    const float* b2      = (const float*)d_in[10];
    const float* g2      = (const float*)d_in[11];
    const float* be2     = (const float*)d_in[12];
    const float* Wout    = (const float*)d_in[13];
    const float* bout    = (const float*)d_in[14];
    float* out = (float*)d_out;

    const int GEMM_GRID = (NN + 63) / 64;   // 1563

    init_kernel<<<(NN + 255) / 256, 256>>>(ei);
    deg_kernel<<<(NE + 255) / 256, 256>>>(ei);
    bn_stats_x_kernel<<<512, 256>>>(x);
    gemm_kernel<<<GEMM_GRID, 256>>>(x, 0, x, 0, bn_in_g, bn_in_b, W1, 0); // conv1 transform
    rsqrt_scanA_kernel<<<SCAN_NB, 256>>>();
    scanB_kernel<<<1, 32>>>();
    scanC_kernel<<<SCAN_NB, 256>>>();
    place_kernel<<<(NE + 255) / 256, 256>>>(ei);
    gather_kernel<<<NN / 16, 512>>>(1, b1, 128);                          // conv1 agg + BN2 stats
    gemm_kernel<<<GEMM_GRID, 256>>>(x, 1, b1, 1, g1, be1, W2, 128);       // conv2 transform
    gather_kernel<<<NN / 16, 512>>>(0, b1, 0);                            // conv2 agg
    pool_kernel<<<512, 256>>>(b2, batch);
    final_kernel<<<4, 256>>>(g2, be2, Wout, bout, out);
}

// round 8
// speedup vs baseline: 1.0142x; 1.0142x over previous
#include <cuda_runtime.h>
#include <cuda_fp16.h>

#define NN 100000
#define NE 1280000
#define FD 64
#define NG 1000
#define BN_EPS 1e-5f
#define SCAN_CH 1024
#define SCAN_NB ((NN + SCAN_CH - 1) / SCAN_CH)   // 98

// ---------------- device scratch (allocation-free rule: __device__ globals) ----
__device__ int    g_deg[NN];
__device__ float  g_dinv[NN];
__device__ __half g_th[(size_t)NN * FD];      // transformed features (fp16 messages)
__device__ float  g_agg[(size_t)NN * FD];     // aggregated features (fp32)
__device__ float  g_stats[6 * FD];            // s1 ss1 | s2 ss2 | s3 ss3
__device__ float  g_gsum[NG * FD];
__device__ float  g_gcnt[NG];
__device__ int    g_is64;
// CSR sorted by destination; packed (src, norm-bits)
__device__ int    g_rowptr[NN + 1];
__device__ int    g_fill[NN];
__device__ int2   g_csr[NE];
__device__ int    g_bsum[SCAN_NB];
__device__ int    g_boff[SCAN_NB];

__device__ __forceinline__ unsigned pack_half2(float a, float b) {
    __half2 h = __floats2half2_rn(a, b);
    return (unsigned)__half_as_ushort(__low2half(h)) |
           ((unsigned)__half_as_ushort(__high2half(h)) << 16);
}

// ---------------- init + dtype detect (block 0 detects int64 via odd words==0)
__global__ void init_kernel(const int* __restrict__ ei) {
    int i = blockIdx.x * blockDim.x + threadIdx.x;
    if (i < NN) g_deg[i] = 0;
    if (i < 6 * FD) g_stats[i] = 0.0f;
    if (i < NG * FD) g_gsum[i] = 0.0f;
    if (i < NG) g_gcnt[i] = 0.0f;
    if (blockIdx.x == 0) {
        __shared__ int nz;
        if (threadIdx.x == 0) nz = 0;
        __syncthreads();
        int local = 0;
        for (int k = threadIdx.x; k < 4096; k += blockDim.x)
            if (ei[2 * k + 1] != 0) local = 1;
        if (local) nz = 1;
        __syncthreads();
        if (threadIdx.x == 0) g_is64 = (nz == 0) ? 1 : 0;
    }
}

__global__ void deg_kernel(const int* __restrict__ ei) {
    int e = blockIdx.x * blockDim.x + threadIdx.x;
    if (e >= NE) return;
    int c = g_is64 ? ei[2 * (NE + e)] : ei[NE + e];
    atomicAdd(&g_deg[c], 1);
}

// ---------------- rsqrt(deg+1) + per-chunk sums (scan level A) --------------
__global__ void rsqrt_scanA_kernel() {
    __shared__ int sh[256];
    int b = blockIdx.x, t = threadIdx.x;
    int base = b * SCAN_CH + t * 4;
    int s = 0;
#pragma unroll
    for (int k = 0; k < 4; k++) {
        int i = base + k;
        if (i < NN) {
            int d = g_deg[i];
            g_dinv[i] = rsqrtf((float)d + 1.0f);
            s += d;
        }
    }
    sh[t] = s;
    __syncthreads();
    for (int off = 128; off > 0; off >>= 1) {
        if (t < off) sh[t] += sh[t + off];
        __syncthreads();
    }
    if (t == 0) g_bsum[b] = sh[0];
}

__global__ void scanB_kernel() {
    if (threadIdx.x == 0) {
        int acc = 0;
        for (int b = 0; b < SCAN_NB; b++) { g_boff[b] = acc; acc += g_bsum[b]; }
        g_rowptr[NN] = acc;
    }
}

__global__ void scanC_kernel() {
    __shared__ int sh[257];
    int b = blockIdx.x, t = threadIdx.x;
    int base = b * SCAN_CH + t * 4;
    int v[4]; int s = 0;
#pragma unroll
    for (int k = 0; k < 4; k++) {
        int i = base + k;
        v[k] = (i < NN) ? g_deg[i] : 0;
        s += v[k];
    }
    sh[t + 1] = s;
    if (t == 0) sh[0] = 0;
    __syncthreads();
    for (int off = 1; off < 256; off <<= 1) {
        int val = (t + 1 > off) ? sh[t + 1 - off] : 0;
        __syncthreads();
        sh[t + 1] += val;
        __syncthreads();
    }
    int run = g_boff[b] + sh[t];
#pragma unroll
    for (int k = 0; k < 4; k++) {
        int i = base + k;
        if (i < NN) { g_rowptr[i] = run; g_fill[i] = run; run += v[k]; }
    }
}

__global__ void place_kernel(const int* __restrict__ ei) {
    int e = blockIdx.x * blockDim.x + threadIdx.x;
    if (e >= NE) return;
    int r, c;
    if (g_is64) { r = ei[2 * e]; c = ei[2 * (NE + e)]; }
    else        { r = ei[e];     c = ei[NE + e]; }
    int pos = atomicAdd(&g_fill[c], 1);
    float nrm = g_dinv[r] * g_dinv[c];
    g_csr[pos] = make_int2(r, __float_as_int(nrm));
}

// ---------------- BN stats for layer-1 input x ------------------------------
__global__ void bn_stats_x_kernel(const float* __restrict__ x) {
    int f   = threadIdx.x & 63;
    int sub = threadIdx.x >> 6;
    float s = 0.0f, ss = 0.0f;
    for (int n = blockIdx.x * 4 + sub; n < NN; n += gridDim.x * 4) {
        float v = x[(size_t)n * FD + f];
        s += v; ss += v * v;
    }
    atomicAdd(&g_stats[f], s);
    atomicAdd(&g_stats[64 + f], ss);
}

// ---------------- GEMM with fused BN fold:  t = prologue(in) @ (diag(a)W) + c@W
// prologue = relu(in + bias) if dorelu.  Output fp16.
// 64 rows/block, 256 threads, 4x4 register blocking.
// Inner loop k-vectorized: per 4 k-steps only 8 LDS.128 feed 64 FFMA
// (the LDS crossbar was the binder at scalar x loads).
__global__ void gemm_kernel(const float* __restrict__ xin, int use_agg,
                            const float* __restrict__ bias, int dorelu,
                            const float* __restrict__ gg, const float* __restrict__ bb,
                            const float* __restrict__ W, int soff) {
    __shared__ float sIn[64 * 68];          // 272B row stride (16B-aligned), conflict-free
    __shared__ float sW[FD * FD];
    __shared__ float sA[FD], sC[FD], sCrow[FD];
    const float* __restrict__ src = use_agg ? g_agg : xin;
    int tid = threadIdx.x;

    // raw W into smem + BN fold coefficients
    for (int i = tid; i < FD * FD; i += 256) sW[i] = W[i];
    if (tid < FD) {
        float m = g_stats[soff + tid] * (1.0f / NN);
        float v = fmaxf(g_stats[soff + 64 + tid] * (1.0f / NN) - m * m, 0.0f);
        float af = gg[tid] * rsqrtf(v + BN_EPS);
        sA[tid] = af;
        sC[tid] = bb[tid] - m * af;
    }
    __syncthreads();

    // input tile load (overlapped with crow compute below)
    int base = blockIdx.x * 64;
    int nrows = min(64, NN - base);
    for (int i = tid; i < 64 * 16; i += 256) {
        int r = i >> 4, kc = i & 15;
        float4 v = make_float4(0.f, 0.f, 0.f, 0.f);
        if (r < nrows) {
            v = ((const float4*)src)[(size_t)(base + r) * 16 + kc];
            if (dorelu) {
                float4 bv = ((const float4*)bias)[kc];
                v.x = fmaxf(v.x + bv.x, 0.0f);
                v.y = fmaxf(v.y + bv.y, 0.0f);
                v.z = fmaxf(v.z + bv.z, 0.0f);
                v.w = fmaxf(v.w + bv.w, 0.0f);
            }
        }
        *((float4*)&sIn[r * 68 + kc * 4]) = v;
    }
    float cr = 0.0f;
    if (tid < FD) {
        for (int i = 0; i < FD; i++) cr += sC[i] * sW[i * FD + tid];
    }
    __syncthreads();

    // scale sW in place, publish crow
    for (int i = tid; i < FD * FD; i += 256) sW[i] *= sA[i >> 6];
    if (tid < FD) sCrow[tid] = cr;
    __syncthreads();

    int rp = tid >> 4, tc = tid & 15;      // rp: 4-row group, tc: 4-col group
    int rbase = rp * 4;
    float4 acc0 = make_float4(0.f, 0.f, 0.f, 0.f);
    float4 acc1 = make_float4(0.f, 0.f, 0.f, 0.f);
    float4 acc2 = make_float4(0.f, 0.f, 0.f, 0.f);
    float4 acc3 = make_float4(0.f, 0.f, 0.f, 0.f);
    const float4* sW4 = (const float4*)sW;
#pragma unroll
    for (int k4 = 0; k4 < 16; k4++) {
        float4 x0 = *(const float4*)&sIn[(rbase + 0) * 68 + k4 * 4];
        float4 x1 = *(const float4*)&sIn[(rbase + 1) * 68 + k4 * 4];
        float4 x2 = *(const float4*)&sIn[(rbase + 2) * 68 + k4 * 4];
        float4 x3 = *(const float4*)&sIn[(rbase + 3) * 68 + k4 * 4];
#pragma unroll
        for (int kk = 0; kk < 4; kk++) {
            float4 w = sW4[(k4 * 4 + kk) * 16 + tc];
            float v0 = kk == 0 ? x0.x : kk == 1 ? x0.y : kk == 2 ? x0.z : x0.w;
            float v1 = kk == 0 ? x1.x : kk == 1 ? x1.y : kk == 2 ? x1.z : x1.w;
            float v2 = kk == 0 ? x2.x : kk == 1 ? x2.y : kk == 2 ? x2.z : x2.w;
            float v3 = kk == 0 ? x3.x : kk == 1 ? x3.y : kk == 2 ? x3.z : x3.w;
            acc0.x += v0 * w.x; acc0.y += v0 * w.y; acc0.z += v0 * w.z; acc0.w += v0 * w.w;
            acc1.x += v1 * w.x; acc1.y += v1 * w.y; acc1.z += v1 * w.z; acc1.w += v1 * w.w;
            acc2.x += v2 * w.x; acc2.y += v2 * w.y; acc2.z += v2 * w.z; acc2.w += v2 * w.w;
            acc3.x += v3 * w.x; acc3.y += v3 * w.y; acc3.z += v3 * w.z; acc3.w += v3 * w.w;
        }
    }
    float4 crw = ((const float4*)sCrow)[tc];
    acc0.x += crw.x; acc0.y += crw.y; acc0.z += crw.z; acc0.w += crw.w;
    acc1.x += crw.x; acc1.y += crw.y; acc1.z += crw.z; acc1.w += crw.w;
    acc2.x += crw.x; acc2.y += crw.y; acc2.z += crw.z; acc2.w += crw.w;
    acc3.x += crw.x; acc3.y += crw.y; acc3.z += crw.z; acc3.w += crw.w;

    uint2* th2 = (uint2*)g_th;
    if (rbase + 0 < nrows) th2[(size_t)(base + rbase + 0) * 16 + tc] = make_uint2(pack_half2(acc0.x, acc0.y), pack_half2(acc0.z, acc0.w));
    if (rbase + 1 < nrows) th2[(size_t)(base + rbase + 1) * 16 + tc] = make_uint2(pack_half2(acc1.x, acc1.y), pack_half2(acc1.z, acc1.w));
    if (rbase + 2 < nrows) th2[(size_t)(base + rbase + 2) * 16 + tc] = make_uint2(pack_half2(acc2.x, acc2.y), pack_half2(acc2.z, acc2.w));
    if (rbase + 3 < nrows) th2[(size_t)(base + rbase + 3) * 16 + tc] = make_uint2(pack_half2(acc3.x, acc3.y), pack_half2(acc3.z, acc3.w));
}

// ---------------- CSR gather conv: warp/node, lane = 2 feats, fp16 messages.
// Optional epilogue: BN stats of relu(agg + bias) via block reduction.
__global__ void gather_kernel(int do_stats, const float* __restrict__ bias, int soff) {
    __shared__ float sStat[128];
    int tid  = threadIdx.x;
    int lane = tid & 31;
    if (do_stats && tid < 128) sStat[tid] = 0.0f;

    int n = (blockIdx.x * blockDim.x + tid) >> 5;   // 16 nodes per 512-thread block
    const __half2* th2 = (const __half2*)g_th;
    float d = g_dinv[n];
    float s = d * d;
    float2 acc = __half22float2(th2[(size_t)n * 32 + lane]);
    acc.x *= s; acc.y *= s;

    int j = g_rowptr[n], end = g_rowptr[n + 1];
    for (; j + 2 <= end; j += 2) {
        int2 p0 = g_csr[j];
        int2 p1 = g_csr[j + 1];
        float2 v0 = __half22float2(th2[(size_t)p0.x * 32 + lane]);
        float2 v1 = __half22float2(th2[(size_t)p1.x * 32 + lane]);
        float w0 = __int_as_float(p0.y), w1 = __int_as_float(p1.y);
        acc.x += v0.x * w0 + v1.x * w1;
        acc.y += v0.y * w0 + v1.y * w1;
    }
    if (j < end) {
        int2 p = g_csr[j];
        float2 v = __half22float2(th2[(size_t)p.x * 32 + lane]);
        float w = __int_as_float(p.y);
        acc.x += v.x * w;
        acc.y += v.y * w;
    }
    ((float2*)g_agg)[(size_t)n * 32 + lane] = acc;

    if (do_stats) {
        float2 bb = ((const float2*)bias)[lane];
        float y0 = fmaxf(acc.x + bb.x, 0.0f);
        float y1 = fmaxf(acc.y + bb.y, 0.0f);
        __syncthreads();             // zero-fill visible, all accs done
        atomicAdd(&sStat[2 * lane],      y0);
        atomicAdd(&sStat[2 * lane + 1],  y1);
        atomicAdd(&sStat[64 + 2 * lane],     y0 * y0);
        atomicAdd(&sStat[64 + 2 * lane + 1], y1 * y1);
        __syncthreads();
        if (tid < 128) atomicAdd(&g_stats[soff + tid], sStat[tid]);
    }
}

// ---------------- pool: y=relu(agg+b2); BN3 stats + per-graph sums (batch sorted)
__global__ void pool_kernel(const float* __restrict__ bias, const int* __restrict__ batch) {
    int f   = threadIdx.x & 63;
    int sub = threadIdx.x >> 6;
    int is64 = g_is64;
    float bs = bias[f];
    const int chunk = 196;                 // 512 blocks * 196 >= NN
    const int subc  = 49;
    int start = blockIdx.x * chunk + sub * subc;
    int stop  = min(start + subc, NN);
    float s = 0.0f, ss = 0.0f;
    int   cur = -1;
    float gv = 0.0f, gc = 0.0f;
    for (int n = start; n < stop; n++) {
        int b = is64 ? batch[2 * n] : batch[n];
        if (b != cur) {
            if (cur >= 0) {
                atomicAdd(&g_gsum[cur * FD + f], gv);
                if (f == 0) atomicAdd(&g_gcnt[cur], gc);
            }
            cur = b; gv = 0.0f; gc = 0.0f;
        }
        float v = fmaxf(g_agg[(size_t)n * FD + f] + bs, 0.0f);
        s += v; ss += v * v;
        gv += v; gc += 1.0f;
    }
    if (cur >= 0) {
        atomicAdd(&g_gsum[cur * FD + f], gv);
        if (f == 0) atomicAdd(&g_gcnt[cur], gc);
    }
    atomicAdd(&g_stats[256 + f], s);
    atomicAdd(&g_stats[320 + f], ss);
}

// ---------------- final: fold BN3 into Wout, emit [NG, 2] --------------------
__global__ void final_kernel(const float* __restrict__ gg, const float* __restrict__ bb,
                             const float* __restrict__ Wout, const float* __restrict__ bout,
                             float* __restrict__ out) {
    __shared__ float sWp[FD * 2];
    __shared__ float sc[FD];
    __shared__ float scb[2];
    int tid = threadIdx.x;
    if (tid < FD) {
        float m = g_stats[256 + tid] * (1.0f / NN);
        float v = fmaxf(g_stats[320 + tid] * (1.0f / NN) - m * m, 0.0f);
        float af = gg[tid] * rsqrtf(v + BN_EPS);
        sc[tid] = bb[tid] - m * af;
        sWp[tid * 2]     = af * Wout[tid * 2];
        sWp[tid * 2 + 1] = af * Wout[tid * 2 + 1];
    }
    __syncthreads();
    if (tid < 2) {
        float acc = bout[tid];
        for (int i = 0; i < FD; i++) acc += sc[i] * Wout[i * 2 + tid];
        scb[tid] = acc;
    }
    __syncthreads();
    int g = blockIdx.x * blockDim.x + tid;
    if (g >= NG) return;
    float cnt = g_gcnt[g];
    if (cnt > 0.0f) {
        float inv = 1.0f / cnt;
        float a0 = scb[0], a1 = scb[1];
#pragma unroll 8
        for (int f = 0; f < FD; f++) {
            float p = g_gsum[g * FD + f] * inv;
            a0 += p * sWp[f * 2];
            a1 += p * sWp[f * 2 + 1];
        }
        out[g * 2] = a0; out[g * 2 + 1] = a1;
    } else {
        out[g * 2] = bout[0]; out[g * 2 + 1] = bout[1];
    }
}

extern "C" void kernel_launch(void* const* d_in, const int* in_sizes, int n_in,
                              void* d_out, int out_size) {
    const float* x       = (const float*)d_in[0];
    const int*   ei      = (const int*)d_in[1];
    const int*   batch   = (const int*)d_in[2];
    const float* bn_in_g = (const float*)d_in[3];
    const float* bn_in_b = (const float*)d_in[4];
    const float* W1      = (const float*)d_in[5];
    const float* b1      = (const float*)d_in[6];
    const float* g1      = (const float*)d_in[7];
    const float* be1     = (const float*)d_in[8];
    const float* W2      = (const float*)d_in[9];
    const float* b2      = (const float*)d_in[10];
    const float* g2      = (const float*)d_in[11];
    const float* be2     = (const float*)d_in[12];
    const float* Wout    = (const float*)d_in[13];
    const float* bout    = (const float*)d_in[14];
    float* out = (float*)d_out;

    const int GEMM_GRID = (NN + 63) / 64;   // 1563

    init_kernel<<<(NN + 255) / 256, 256>>>(ei);
    deg_kernel<<<(NE + 255) / 256, 256>>>(ei);
    bn_stats_x_kernel<<<512, 256>>>(x);
    gemm_kernel<<<GEMM_GRID, 256>>>(x, 0, x, 0, bn_in_g, bn_in_b, W1, 0); // conv1 transform
    rsqrt_scanA_kernel<<<SCAN_NB, 256>>>();
    scanB_kernel<<<1, 32>>>();
    scanC_kernel<<<SCAN_NB, 256>>>();
    place_kernel<<<(NE + 255) / 256, 256>>>(ei);
    gather_kernel<<<NN / 16, 512>>>(1, b1, 128);                          // conv1 agg + BN2 stats
    gemm_kernel<<<GEMM_GRID, 256>>>(x, 1, b1, 1, g1, be1, W2, 128);       // conv2 transform
    gather_kernel<<<NN / 16, 512>>>(0, b1, 0);                            // conv2 agg
    pool_kernel<<<512, 256>>>(b2, batch);
    final_kernel<<<4, 256>>>(g2, be2, Wout, bout, out);
}